// round 8
// baseline (speedup 1.0000x reference)
#include <cuda_runtime.h>
#include <cuda_bf16.h>
#include <cstdint>

// Problem constants
#define BB 4
#define SS 2048
#define DD 768
#define HH 12
#define DH 64
#define BH (BB*HH)          // 48

// Scratch: Q [bh][s][dh] (tf32, pre-scaled 0.125), K [bh][s][dh] (tf32),
//          V TRANSPOSED [bh][dh][s] (tf32)
__device__ float g_q[BH * SS * DH];
__device__ float g_k[BH * SS * DH];
__device__ float g_v[BH * SS * DH];

// ---------------------------------------------------------------------------
// Helpers
// ---------------------------------------------------------------------------
__device__ __forceinline__ float tf32r(float x) {
    uint32_t u;
    asm("cvt.rna.tf32.f32 %0, %1;" : "=r"(u) : "f"(x));
    return __uint_as_float(u);
}
__device__ __forceinline__ void ldsm_x4(uint32_t& r0, uint32_t& r1, uint32_t& r2, uint32_t& r3, uint32_t a) {
    asm volatile("ldmatrix.sync.aligned.m8n8.x4.shared.b16 {%0,%1,%2,%3}, [%4];"
                 : "=r"(r0), "=r"(r1), "=r"(r2), "=r"(r3) : "r"(a));
}
__device__ __forceinline__ void ldsm_x2(uint32_t& r0, uint32_t& r1, uint32_t a) {
    asm volatile("ldmatrix.sync.aligned.m8n8.x2.shared.b16 {%0,%1}, [%2];"
                 : "=r"(r0), "=r"(r1) : "r"(a));
}
__device__ __forceinline__ void mma_tf32(float (&d)[4],
                                         uint32_t a0, uint32_t a1, uint32_t a2, uint32_t a3,
                                         uint32_t b0, uint32_t b1) {
    asm volatile("mma.sync.aligned.m16n8k8.row.col.f32.tf32.tf32.f32 "
                 "{%0,%1,%2,%3}, {%4,%5,%6,%7}, {%8,%9}, {%0,%1,%2,%3};"
                 : "+f"(d[0]), "+f"(d[1]), "+f"(d[2]), "+f"(d[3])
                 : "r"(a0), "r"(a1), "r"(a2), "r"(a3), "r"(b0), "r"(b1));
}
__device__ __forceinline__ void cpa16(uint32_t dst, const float* src) {
    asm volatile("cp.async.cg.shared.global [%0], [%1], 16;" :: "r"(dst), "l"(src));
}
__device__ __forceinline__ void cpa_commit() {
    asm volatile("cp.async.commit_group;");
}
template <int N>
__device__ __forceinline__ void cpa_wait() {
    asm volatile("cp.async.wait_group %0;" :: "n"(N));
}

// ---------------------------------------------------------------------------
// Kernel 1: fused QKV projection, tf32 mma.sync, K-step 32, register-staged
// software pipeline (LDG of tile t+1 overlaps compute of tile t).
// 256 threads, 8 warps m32 x n64. grid = (64, 6, 3), 2 CTAs/SM.
// ---------------------------------------------------------------------------
#define KS 32
#define XRW 36   // 32 k + 4 pad

__global__ __launch_bounds__(256, 2)
void qkv_kernel(const float* __restrict__ X,
                const float* __restrict__ Wq, const float* __restrict__ bq,
                const float* __restrict__ Wk, const float* __restrict__ bk,
                const float* __restrict__ Wv, const float* __restrict__ bv)
{
    __shared__ float Xs[128 * XRW];   // [m][k]
    __shared__ float Ws[128 * XRW];   // [n][k] (W transposed)

    const int z = blockIdx.z;
    const float* W    = (z == 0) ? Wq : (z == 1) ? Wk : Wv;
    const float* bias = (z == 0) ? bq : (z == 1) ? bk : bv;
    float* out        = (z == 0) ? g_q : (z == 1) ? g_k : g_v;

    const int bm = blockIdx.x;
    const int bn = blockIdx.y;
    const int tid = threadIdx.x;
    const int w = tid >> 5;
    const int l = tid & 31;
    const int tg = l & 3;
    const int grp = l >> 2;

    const int warpM = (w >> 1) * 32;
    const int warpN = (w & 1) * 64;

    const uint32_t xs_u = (uint32_t)__cvta_generic_to_shared(Xs);
    const uint32_t ws_u = (uint32_t)__cvta_generic_to_shared(Ws);

    const uint32_t aX0 = xs_u + (uint32_t)((warpM + (l & 15)) * XRW + (l >> 4) * 4) * 4u;
    const uint32_t aX1 = aX0 + 16u * XRW * 4u;
    const uint32_t bW  = ws_u + (uint32_t)((warpN + (l & 7)) * XRW + ((l >> 3) & 1) * 4) * 4u;

    // staging-load index maps
    const int xr_row = tid >> 1;              // 0..127
    const int xr_cb  = (tid & 1) * 16;        // float col base 0 or 16
    const int w_kb   = tid & 7;               // k block (4 wide) 0..7
    const int w_nb   = tid >> 3;              // n block (4 wide) 0..31

    const float* Xg = X + (size_t)(bm * 128 + xr_row) * DD + xr_cb;
    const float* Wg = W + (size_t)(w_kb * 4) * DD + bn * 128 + w_nb * 4;

    float4 xr[4], wr[4];

    // ---- prologue: load tile 0 into regs
#pragma unroll
    for (int j = 0; j < 4; j++) xr[j] = *(const float4*)(Xg + j * 4);
#pragma unroll
    for (int j = 0; j < 4; j++) wr[j] = *(const float4*)(Wg + (size_t)j * DD);

    float acc[2][8][4];
#pragma unroll
    for (int m2 = 0; m2 < 2; m2++)
#pragma unroll
        for (int n = 0; n < 8; n++)
#pragma unroll
            for (int j = 0; j < 4; j++) acc[m2][n][j] = 0.f;

    const int NITER = DD / KS;   // 24
    for (int t = 0; t < NITER; t++) {
        // ---- store staged regs to smem (tf32 rounding; W transposed)
        {
            float* xd = Xs + xr_row * XRW + xr_cb;
#pragma unroll
            for (int j = 0; j < 4; j++)
                *(float4*)(xd + j * 4) =
                    make_float4(tf32r(xr[j].x), tf32r(xr[j].y), tf32r(xr[j].z), tf32r(xr[j].w));
            float* wd = Ws + (w_nb * 4) * XRW + w_kb * 4;
            *(float4*)(wd + 0 * XRW) = make_float4(tf32r(wr[0].x), tf32r(wr[1].x), tf32r(wr[2].x), tf32r(wr[3].x));
            *(float4*)(wd + 1 * XRW) = make_float4(tf32r(wr[0].y), tf32r(wr[1].y), tf32r(wr[2].y), tf32r(wr[3].y));
            *(float4*)(wd + 2 * XRW) = make_float4(tf32r(wr[0].z), tf32r(wr[1].z), tf32r(wr[2].z), tf32r(wr[3].z));
            *(float4*)(wd + 3 * XRW) = make_float4(tf32r(wr[0].w), tf32r(wr[1].w), tf32r(wr[2].w), tf32r(wr[3].w));
        }
        __syncthreads();

        // ---- issue LDG for tile t+1 (overlaps the mma section below)
        if (t + 1 < NITER) {
            const int k0 = (t + 1) * KS;
#pragma unroll
            for (int j = 0; j < 4; j++) xr[j] = *(const float4*)(Xg + k0 + j * 4);
#pragma unroll
            for (int j = 0; j < 4; j++) wr[j] = *(const float4*)(Wg + (size_t)(k0 + j) * DD);
        }

        // ---- compute: 4 k8 sub-steps x (2 m16 x 8 n8)
#pragma unroll
        for (int kk = 0; kk < 4; kk++) {
            const uint32_t koff = kk * 32u;
            uint32_t a0[4], a1[4];
            ldsm_x4(a0[0], a0[1], a0[2], a0[3], aX0 + koff);
            ldsm_x4(a1[0], a1[1], a1[2], a1[3], aX1 + koff);
#pragma unroll
            for (int n = 0; n < 8; n++) {
                uint32_t b0, b1;
                ldsm_x2(b0, b1, bW + (uint32_t)(n * 8 * XRW) * 4u + koff);
                mma_tf32(acc[0][n], a0[0], a0[1], a0[2], a0[3], b0, b1);
                mma_tf32(acc[1][n], a1[0], a1[1], a1[2], a1[3], b0, b1);
            }
        }
        __syncthreads();   // smem reads done before next store
    }

    // ---- epilogue: add bias, round to tf32, store (Q scaled; V transposed)
#pragma unroll
    for (int m2 = 0; m2 < 2; m2++) {
        const int m0 = bm * 128 + warpM + m2 * 16 + grp;
#pragma unroll
        for (int half = 0; half < 2; half++) {
            const int m = m0 + half * 8;
            const int b = m >> 11;
            const int s = m & 2047;
#pragma unroll
            for (int n = 0; n < 8; n++) {
                const int col = bn * 128 + warpN + n * 8 + 2 * tg;
                const int h = col >> 6;
                const int dh = col & 63;
                float c0 = acc[m2][n][half * 2 + 0] + __ldg(&bias[col]);
                float c1 = acc[m2][n][half * 2 + 1] + __ldg(&bias[col + 1]);
                if (z == 0) {
                    *(float2*)(out + ((size_t)(b * HH + h) * SS + s) * DH + dh) =
                        make_float2(tf32r(c0 * 0.125f), tf32r(c1 * 0.125f));
                } else if (z == 1) {
                    *(float2*)(out + ((size_t)(b * HH + h) * SS + s) * DH + dh) =
                        make_float2(tf32r(c0), tf32r(c1));
                } else {
                    float* vb = out + ((size_t)(b * HH + h) * DH + dh) * SS + s;
                    vb[0]  = tf32r(c0);
                    vb[SS] = tf32r(c1);
                }
            }
        }
    }
}

// ---------------------------------------------------------------------------
// Kernel 2: flash attention, tf32 mma.sync, m32 warp tile, cp.async
// double-buffered K/V — unchanged from R7.
// ---------------------------------------------------------------------------
#define RW 68
#define K_OFF(buf) ((buf) * 64 * RW)
#define V_OFF(buf) ((2 + (buf)) * 64 * RW)
#define PS_OFF     (4 * 64 * RW)
#define MS_OFF     (PS_OFF + 128 * RW)
#define SMF        (MS_OFF + SS)          // 28160 floats = 112640 B

__global__ __launch_bounds__(128, 2)
void attn_kernel(const float* __restrict__ mask, float* __restrict__ out)
{
    extern __shared__ float sm[];
    float* Ps = sm + PS_OFF;
    float* Ms = sm + MS_OFF;

    const int tid = threadIdx.x;
    const int w = tid >> 5;
    const int l = tid & 31;
    const int tg = l & 3;
    const int grp = l >> 2;

    const int bh = blockIdx.y;
    const int b = bh / HH;
    const int h = bh % HH;
    const int q0 = blockIdx.x * 128;

    const float* Qg  = g_q + (size_t)bh * SS * DH;
    const float* Kg  = g_k + (size_t)bh * SS * DH;
    const float* VgT = g_v + (size_t)bh * SS * DH;   // [dh][s]
    const float* mrow = mask + (size_t)b * SS;

    const uint32_t sm_u = (uint32_t)__cvta_generic_to_shared(sm);
    const uint32_t ps_u = sm_u + PS_OFF * 4u;

    const uint32_t aP0 = ps_u + (uint32_t)((w * 32 + (l & 15)) * RW + (l >> 4) * 4) * 4u;
    const uint32_t aP1 = aP0 + 16u * RW * 4u;
    const uint32_t bLane = (uint32_t)(((l & 7)) * RW + ((l >> 3) & 1) * 4) * 4u;

    // ---- prologue: issue tile 0 (K,V) + mask row as cp.async group 0
    {
#pragma unroll
        for (int it = 0; it < 8; it++) {
            const int idx = it * 128 + tid;
            const int r = idx >> 4, c = idx & 15;
            cpa16(sm_u + (uint32_t)(K_OFF(0) + r * RW + c * 4) * 4u,
                  Kg + (size_t)r * DH + c * 4);
        }
#pragma unroll
        for (int it = 0; it < 8; it++) {
            const int idx = it * 128 + tid;
            const int d = idx >> 4, c = idx & 15;
            cpa16(sm_u + (uint32_t)(V_OFF(0) + d * RW + c * 4) * 4u,
                  VgT + (size_t)d * SS + c * 4);
        }
#pragma unroll
        for (int it = 0; it < 4; it++) {
            const int c = it * 128 + tid;
            cpa16(sm_u + (uint32_t)(MS_OFF + c * 4) * 4u, mrow + c * 4);
        }
        cpa_commit();
    }

    // ---- stage Q tile into Ps, load Q fragments to registers
#pragma unroll
    for (int it = 0; it < 16; it++) {
        const int i = it * 128 + tid;
        const int r = i >> 4, c4 = i & 15;
        *(float4*)(Ps + r * RW + c4 * 4) =
            *(const float4*)(Qg + (size_t)(q0 + r) * DH + c4 * 4);
    }
    __syncthreads();

    uint32_t qf[2][8][4];
    {
        const uint32_t aQ0 = ps_u + (uint32_t)((w * 32 + (l & 15)) * RW + (l >> 4) * 4) * 4u;
#pragma unroll
        for (int mt = 0; mt < 2; mt++)
#pragma unroll
            for (int kk = 0; kk < 8; kk++)
                ldsm_x4(qf[mt][kk][0], qf[mt][kk][1], qf[mt][kk][2], qf[mt][kk][3],
                        aQ0 + (uint32_t)(mt * 16 * RW) * 4u + kk * 32u);
    }

    float o[2][8][4];
#pragma unroll
    for (int mt = 0; mt < 2; mt++)
#pragma unroll
        for (int n = 0; n < 8; n++)
#pragma unroll
            for (int j = 0; j < 4; j++) o[mt][n][j] = 0.f;
    float mr[4], lr[4];
#pragma unroll
    for (int i = 0; i < 4; i++) { mr[i] = -1e30f; lr[i] = 0.f; }

    const int NT = SS / 64;
    for (int t = 0; t < NT; t++) {
        const int buf = t & 1;
        const uint32_t kBase = sm_u + (uint32_t)K_OFF(buf) * 4u + bLane;
        const uint32_t vBase = sm_u + (uint32_t)V_OFF(buf) * 4u + bLane;

        if (t + 1 < NT) {
            const int nb = 1 - buf;
            const int nk0 = (t + 1) * 64;
#pragma unroll
            for (int it = 0; it < 8; it++) {
                const int idx = it * 128 + tid;
                const int r = idx >> 4, c = idx & 15;
                cpa16(sm_u + (uint32_t)(K_OFF(nb) + r * RW + c * 4) * 4u,
                      Kg + (size_t)(nk0 + r) * DH + c * 4);
            }
#pragma unroll
            for (int it = 0; it < 8; it++) {
                const int idx = it * 128 + tid;
                const int d = idx >> 4, c = idx & 15;
                cpa16(sm_u + (uint32_t)(V_OFF(nb) + d * RW + c * 4) * 4u,
                      VgT + (size_t)d * SS + nk0 + c * 4);
            }
            cpa_commit();
            cpa_wait<1>();
        } else {
            cpa_wait<0>();
        }
        __syncthreads();

        float s[2][8][4];
#pragma unroll
        for (int mt = 0; mt < 2; mt++)
#pragma unroll
            for (int n = 0; n < 8; n++)
#pragma unroll
                for (int j = 0; j < 4; j++) s[mt][n][j] = 0.f;

#pragma unroll
        for (int kk = 0; kk < 8; kk++) {
#pragma unroll
            for (int n = 0; n < 8; n++) {
                uint32_t b0, b1;
                ldsm_x2(b0, b1, kBase + (uint32_t)(n * 8 * RW) * 4u + kk * 32u);
                mma_tf32(s[0][n], qf[0][kk][0], qf[0][kk][1], qf[0][kk][2], qf[0][kk][3], b0, b1);
                mma_tf32(s[1][n], qf[1][kk][0], qf[1][kk][1], qf[1][kk][2], qf[1][kk][3], b0, b1);
            }
        }

        const int k0 = t * 64;
        float rx[4] = {-1e30f, -1e30f, -1e30f, -1e30f};
#pragma unroll
        for (int mt = 0; mt < 2; mt++)
#pragma unroll
            for (int n = 0; n < 8; n++) {
                const float mk0 = Ms[k0 + n * 8 + 2 * tg];
                const float mk1 = Ms[k0 + n * 8 + 2 * tg + 1];
                s[mt][n][0] += mk0; s[mt][n][1] += mk1;
                s[mt][n][2] += mk0; s[mt][n][3] += mk1;
                rx[mt * 2 + 0] = fmaxf(rx[mt * 2 + 0], fmaxf(s[mt][n][0], s[mt][n][1]));
                rx[mt * 2 + 1] = fmaxf(rx[mt * 2 + 1], fmaxf(s[mt][n][2], s[mt][n][3]));
            }
#pragma unroll
        for (int i = 0; i < 4; i++) {
            rx[i] = fmaxf(rx[i], __shfl_xor_sync(0xffffffffu, rx[i], 1));
            rx[i] = fmaxf(rx[i], __shfl_xor_sync(0xffffffffu, rx[i], 2));
        }
        float mn[4], cc[4], sum[4];
#pragma unroll
        for (int i = 0; i < 4; i++) {
            mn[i] = fmaxf(mr[i], rx[i]);
            cc[i] = __expf(mr[i] - mn[i]);
            sum[i] = 0.f;
        }
        const int rowb = w * 32 + grp;
#pragma unroll
        for (int mt = 0; mt < 2; mt++) {
            const int r0 = rowb + mt * 16;
#pragma unroll
            for (int n = 0; n < 8; n++) {
                const float p00 = __expf(s[mt][n][0] - mn[mt * 2]);
                const float p01 = __expf(s[mt][n][1] - mn[mt * 2]);
                const float p10 = __expf(s[mt][n][2] - mn[mt * 2 + 1]);
                const float p11 = __expf(s[mt][n][3] - mn[mt * 2 + 1]);
                sum[mt * 2]     += p00 + p01;
                sum[mt * 2 + 1] += p10 + p11;
                *(float2*)(Ps + r0 * RW + n * 8 + 2 * tg)       = make_float2(tf32r(p00), tf32r(p01));
                *(float2*)(Ps + (r0 + 8) * RW + n * 8 + 2 * tg) = make_float2(tf32r(p10), tf32r(p11));
            }
        }
#pragma unroll
        for (int i = 0; i < 4; i++) {
            sum[i] += __shfl_xor_sync(0xffffffffu, sum[i], 1);
            sum[i] += __shfl_xor_sync(0xffffffffu, sum[i], 2);
            lr[i] = lr[i] * cc[i] + sum[i];
            mr[i] = mn[i];
        }
#pragma unroll
        for (int mt = 0; mt < 2; mt++)
#pragma unroll
            for (int n = 0; n < 8; n++) {
                o[mt][n][0] *= cc[mt * 2];     o[mt][n][1] *= cc[mt * 2];
                o[mt][n][2] *= cc[mt * 2 + 1]; o[mt][n][3] *= cc[mt * 2 + 1];
            }
        __syncwarp();

#pragma unroll
        for (int kk = 0; kk < 8; kk++) {
            uint32_t a0[4], a1[4];
            ldsm_x4(a0[0], a0[1], a0[2], a0[3], aP0 + kk * 32u);
            ldsm_x4(a1[0], a1[1], a1[2], a1[3], aP1 + kk * 32u);
#pragma unroll
            for (int n = 0; n < 8; n++) {
                uint32_t b0, b1;
                ldsm_x2(b0, b1, vBase + (uint32_t)(n * 8 * RW) * 4u + kk * 32u);
                mma_tf32(o[0][n], a0[0], a0[1], a0[2], a0[3], b0, b1);
                mma_tf32(o[1][n], a1[0], a1[1], a1[2], a1[3], b0, b1);
            }
        }
        __syncthreads();
    }

#pragma unroll
    for (int mt = 0; mt < 2; mt++) {
#pragma unroll
        for (int half = 0; half < 2; half++) {
            const int i = mt * 2 + half;
            const float inv = 1.0f / lr[i];
            const int r = q0 + w * 32 + mt * 16 + half * 8 + grp;
#pragma unroll
            for (int n = 0; n < 8; n++) {
                const int col = h * DH + n * 8 + 2 * tg;
                *(float2*)(out + (size_t)(b * SS + r) * DD + col) =
                    make_float2(o[mt][n][half * 2] * inv, o[mt][n][half * 2 + 1] * inv);
            }
        }
    }
}

// ---------------------------------------------------------------------------
extern "C" void kernel_launch(void* const* d_in, const int* in_sizes, int n_in,
                              void* d_out, int out_size)
{
    const float* hidden = (const float*)d_in[0];
    const float* mask   = (const float*)d_in[1];
    const float* Wq     = (const float*)d_in[2];
    const float* bq     = (const float*)d_in[3];
    const float* Wk     = (const float*)d_in[4];
    const float* bk     = (const float*)d_in[5];
    const float* Wv     = (const float*)d_in[6];
    const float* bv     = (const float*)d_in[7];
    float* out = (float*)d_out;

    const int smem_attn = SMF * sizeof(float);   // 112640 B
    cudaFuncSetAttribute(attn_kernel, cudaFuncAttributeMaxDynamicSharedMemorySize, smem_attn);

    qkv_kernel<<<dim3(64, 6, 3), 256>>>(hidden, Wq, bq, Wk, bk, Wv, bv);
    attn_kernel<<<dim3(SS / 128, BH), 128, smem_attn>>>(mask, out);
}

// round 9
// speedup vs baseline: 1.1917x; 1.1917x over previous
#include <cuda_runtime.h>
#include <cuda_bf16.h>
#include <cstdint>

// Problem constants
#define BB 4
#define SS 2048
#define DD 768
#define HH 12
#define DH 64
#define BH (BB*HH)          // 48

// Scratch
__device__ float g_q[BH * SS * DH];      // Q [bh][s][dh], tf32, pre-scaled 0.125
__device__ float g_k[BH * SS * DH];      // K [bh][s][dh], tf32
__device__ float g_v[BH * SS * DH];      // V transposed [bh][dh][s], tf32
__device__ float g_wt[3 * DD * DD];      // W transposed [z][n][k], tf32
__device__ float g_x[BB * SS * DD];      // X [m][k], tf32

// ---------------------------------------------------------------------------
// Helpers
// ---------------------------------------------------------------------------
__device__ __forceinline__ float tf32r(float x) {
    uint32_t u;
    asm("cvt.rna.tf32.f32 %0, %1;" : "=r"(u) : "f"(x));
    return __uint_as_float(u);
}
__device__ __forceinline__ void ldsm_x4(uint32_t& r0, uint32_t& r1, uint32_t& r2, uint32_t& r3, uint32_t a) {
    asm volatile("ldmatrix.sync.aligned.m8n8.x4.shared.b16 {%0,%1,%2,%3}, [%4];"
                 : "=r"(r0), "=r"(r1), "=r"(r2), "=r"(r3) : "r"(a));
}
__device__ __forceinline__ void ldsm_x2(uint32_t& r0, uint32_t& r1, uint32_t a) {
    asm volatile("ldmatrix.sync.aligned.m8n8.x2.shared.b16 {%0,%1}, [%2];"
                 : "=r"(r0), "=r"(r1) : "r"(a));
}
__device__ __forceinline__ void mma_tf32(float (&d)[4],
                                         uint32_t a0, uint32_t a1, uint32_t a2, uint32_t a3,
                                         uint32_t b0, uint32_t b1) {
    asm volatile("mma.sync.aligned.m16n8k8.row.col.f32.tf32.tf32.f32 "
                 "{%0,%1,%2,%3}, {%4,%5,%6,%7}, {%8,%9}, {%0,%1,%2,%3};"
                 : "+f"(d[0]), "+f"(d[1]), "+f"(d[2]), "+f"(d[3])
                 : "r"(a0), "r"(a1), "r"(a2), "r"(a3), "r"(b0), "r"(b1));
}
__device__ __forceinline__ void cpa16(uint32_t dst, const float* src) {
    asm volatile("cp.async.cg.shared.global [%0], [%1], 16;" :: "r"(dst), "l"(src));
}
__device__ __forceinline__ void cpa_commit() {
    asm volatile("cp.async.commit_group;");
}
template <int N>
__device__ __forceinline__ void cpa_wait() {
    asm volatile("cp.async.wait_group %0;" :: "n"(N));
}

// ---------------------------------------------------------------------------
// Prep kernel A: transpose + tf32-round W -> g_wt [z][n][k]
// grid (24, 24, 3), block (32, 8)
// ---------------------------------------------------------------------------
__global__ void prep_w(const float* __restrict__ Wq,
                       const float* __restrict__ Wk,
                       const float* __restrict__ Wv)
{
    __shared__ float t[32][33];
    const int z = blockIdx.z;
    const float* W = (z == 0) ? Wq : (z == 1) ? Wk : Wv;
    float* out = g_wt + (size_t)z * DD * DD;

    const int kx = blockIdx.x * 32;
    const int ny = blockIdx.y * 32;
#pragma unroll
    for (int i = 0; i < 32; i += 8)
        t[threadIdx.y + i][threadIdx.x] =
            tf32r(W[(size_t)(kx + threadIdx.y + i) * DD + ny + threadIdx.x]);
    __syncthreads();
#pragma unroll
    for (int i = 0; i < 32; i += 8)
        out[(size_t)(ny + threadIdx.y + i) * DD + kx + threadIdx.x] =
            t[threadIdx.x][threadIdx.y + i];
}

// ---------------------------------------------------------------------------
// Prep kernel B: tf32-round X -> g_x.  grid 6144, block 256 (float4 each)
// ---------------------------------------------------------------------------
__global__ void prep_x(const float* __restrict__ X)
{
    const size_t i = (size_t)blockIdx.x * blockDim.x + threadIdx.x;
    float4 v = ((const float4*)X)[i];
    ((float4*)g_x)[i] = make_float4(tf32r(v.x), tf32r(v.y), tf32r(v.z), tf32r(v.w));
}

// ---------------------------------------------------------------------------
// Kernel 1: QKV projection, tf32 mma.sync, cp.async double-buffered K-step 32.
// 256 threads, 8 warps m32 x n64. grid = (64, 6, 3), 2 CTAs/SM.
// ---------------------------------------------------------------------------
#define QKRW 36   // 32 k + 4 pad
#define XB(b) ((b) * 128 * QKRW)
#define WBUF(b) ((2 + (b)) * 128 * QKRW)
#define QKV_SMF (4 * 128 * QKRW)          // 18432 floats = 73728 B

__global__ __launch_bounds__(256, 2)
void qkv_kernel(const float* __restrict__ bq,
                const float* __restrict__ bk,
                const float* __restrict__ bv)
{
    extern __shared__ float qsm[];

    const int z = blockIdx.z;
    const float* bias = (z == 0) ? bq : (z == 1) ? bk : bv;
    float* out        = (z == 0) ? g_q : (z == 1) ? g_k : g_v;
    const float* Wt   = g_wt + (size_t)z * DD * DD;

    const int bm = blockIdx.x;
    const int bn = blockIdx.y;
    const int tid = threadIdx.x;
    const int w = tid >> 5;
    const int l = tid & 31;
    const int tg = l & 3;
    const int grp = l >> 2;

    const int warpM = (w >> 1) * 32;
    const int warpN = (w & 1) * 64;

    const uint32_t sm_u = (uint32_t)__cvta_generic_to_shared(qsm);

    const float* Xg = g_x + (size_t)(bm * 128) * DD;
    const float* Wg = Wt + (size_t)(bn * 128) * DD;

    // cp.async index map: 1024 cpa16 per tile / 256 thr = 4 each
    // idx -> row r = idx>>3, 16B chunk c = idx&7
    // prologue: tile 0
    {
#pragma unroll
        for (int it = 0; it < 4; it++) {
            const int idx = it * 256 + tid;
            const int r = idx >> 3, c = idx & 7;
            cpa16(sm_u + (uint32_t)(XB(0) + r * QKRW + c * 4) * 4u,
                  Xg + (size_t)r * DD + c * 4);
        }
#pragma unroll
        for (int it = 0; it < 4; it++) {
            const int idx = it * 256 + tid;
            const int r = idx >> 3, c = idx & 7;
            cpa16(sm_u + (uint32_t)(WBUF(0) + r * QKRW + c * 4) * 4u,
                  Wg + (size_t)r * DD + c * 4);
        }
        cpa_commit();
    }

    float acc[2][8][4];
#pragma unroll
    for (int m2 = 0; m2 < 2; m2++)
#pragma unroll
        for (int n = 0; n < 8; n++)
#pragma unroll
            for (int j = 0; j < 4; j++) acc[m2][n][j] = 0.f;

    const int NITER = DD / 32;   // 24
    for (int t = 0; t < NITER; t++) {
        const int buf = t & 1;

        if (t + 1 < NITER) {
            const int nb = 1 - buf;
            const int k0 = (t + 1) * 32;
#pragma unroll
            for (int it = 0; it < 4; it++) {
                const int idx = it * 256 + tid;
                const int r = idx >> 3, c = idx & 7;
                cpa16(sm_u + (uint32_t)(XB(nb) + r * QKRW + c * 4) * 4u,
                      Xg + (size_t)r * DD + k0 + c * 4);
            }
#pragma unroll
            for (int it = 0; it < 4; it++) {
                const int idx = it * 256 + tid;
                const int r = idx >> 3, c = idx & 7;
                cpa16(sm_u + (uint32_t)(WBUF(nb) + r * QKRW + c * 4) * 4u,
                      Wg + (size_t)r * DD + k0 + c * 4);
            }
            cpa_commit();
            cpa_wait<1>();
        } else {
            cpa_wait<0>();
        }
        __syncthreads();

        const uint32_t aX0 = sm_u + (uint32_t)(XB(buf) + (warpM + (l & 15)) * QKRW + (l >> 4) * 4) * 4u;
        const uint32_t aX1 = aX0 + 16u * QKRW * 4u;
        const uint32_t bW  = sm_u + (uint32_t)(WBUF(buf) + (warpN + (l & 7)) * QKRW + ((l >> 3) & 1) * 4) * 4u;

#pragma unroll
        for (int kk = 0; kk < 4; kk++) {
            const uint32_t koff = kk * 32u;
            uint32_t a0[4], a1[4];
            ldsm_x4(a0[0], a0[1], a0[2], a0[3], aX0 + koff);
            ldsm_x4(a1[0], a1[1], a1[2], a1[3], aX1 + koff);
#pragma unroll
            for (int n = 0; n < 8; n++) {
                uint32_t b0, b1;
                ldsm_x2(b0, b1, bW + (uint32_t)(n * 8 * QKRW) * 4u + koff);
                mma_tf32(acc[0][n], a0[0], a0[1], a0[2], a0[3], b0, b1);
                mma_tf32(acc[1][n], a1[0], a1[1], a1[2], a1[3], b0, b1);
            }
        }
        __syncthreads();
    }

    // ---- epilogue: add bias, round to tf32, store (Q scaled; V transposed)
#pragma unroll
    for (int m2 = 0; m2 < 2; m2++) {
        const int m0 = bm * 128 + warpM + m2 * 16 + grp;
#pragma unroll
        for (int half = 0; half < 2; half++) {
            const int m = m0 + half * 8;
            const int b = m >> 11;
            const int s = m & 2047;
#pragma unroll
            for (int n = 0; n < 8; n++) {
                const int col = bn * 128 + warpN + n * 8 + 2 * tg;
                const int h = col >> 6;
                const int dh = col & 63;
                float c0 = acc[m2][n][half * 2 + 0] + __ldg(&bias[col]);
                float c1 = acc[m2][n][half * 2 + 1] + __ldg(&bias[col + 1]);
                if (z == 0) {
                    *(float2*)(out + ((size_t)(b * HH + h) * SS + s) * DH + dh) =
                        make_float2(tf32r(c0 * 0.125f), tf32r(c1 * 0.125f));
                } else if (z == 1) {
                    *(float2*)(out + ((size_t)(b * HH + h) * SS + s) * DH + dh) =
                        make_float2(tf32r(c0), tf32r(c1));
                } else {
                    float* vb = out + ((size_t)(b * HH + h) * DH + dh) * SS + s;
                    vb[0]  = tf32r(c0);
                    vb[SS] = tf32r(c1);
                }
            }
        }
    }
}

// ---------------------------------------------------------------------------
// Kernel 2: flash attention — unchanged from R7 (best measured config).
// ---------------------------------------------------------------------------
#define RW 68
#define K_OFF(buf) ((buf) * 64 * RW)
#define V_OFF(buf) ((2 + (buf)) * 64 * RW)
#define PS_OFF     (4 * 64 * RW)
#define MS_OFF     (PS_OFF + 128 * RW)
#define SMF        (MS_OFF + SS)          // 28160 floats = 112640 B

__global__ __launch_bounds__(128, 2)
void attn_kernel(const float* __restrict__ mask, float* __restrict__ out)
{
    extern __shared__ float sm[];
    float* Ps = sm + PS_OFF;
    float* Ms = sm + MS_OFF;

    const int tid = threadIdx.x;
    const int w = tid >> 5;
    const int l = tid & 31;
    const int tg = l & 3;
    const int grp = l >> 2;

    const int bh = blockIdx.y;
    const int b = bh / HH;
    const int h = bh % HH;
    const int q0 = blockIdx.x * 128;

    const float* Qg  = g_q + (size_t)bh * SS * DH;
    const float* Kg  = g_k + (size_t)bh * SS * DH;
    const float* VgT = g_v + (size_t)bh * SS * DH;
    const float* mrow = mask + (size_t)b * SS;

    const uint32_t sm_u = (uint32_t)__cvta_generic_to_shared(sm);
    const uint32_t ps_u = sm_u + PS_OFF * 4u;

    const uint32_t aP0 = ps_u + (uint32_t)((w * 32 + (l & 15)) * RW + (l >> 4) * 4) * 4u;
    const uint32_t aP1 = aP0 + 16u * RW * 4u;
    const uint32_t bLane = (uint32_t)(((l & 7)) * RW + ((l >> 3) & 1) * 4) * 4u;

    {
#pragma unroll
        for (int it = 0; it < 8; it++) {
            const int idx = it * 128 + tid;
            const int r = idx >> 4, c = idx & 15;
            cpa16(sm_u + (uint32_t)(K_OFF(0) + r * RW + c * 4) * 4u,
                  Kg + (size_t)r * DH + c * 4);
        }
#pragma unroll
        for (int it = 0; it < 8; it++) {
            const int idx = it * 128 + tid;
            const int d = idx >> 4, c = idx & 15;
            cpa16(sm_u + (uint32_t)(V_OFF(0) + d * RW + c * 4) * 4u,
                  VgT + (size_t)d * SS + c * 4);
        }
#pragma unroll
        for (int it = 0; it < 4; it++) {
            const int c = it * 128 + tid;
            cpa16(sm_u + (uint32_t)(MS_OFF + c * 4) * 4u, mrow + c * 4);
        }
        cpa_commit();
    }

#pragma unroll
    for (int it = 0; it < 16; it++) {
        const int i = it * 128 + tid;
        const int r = i >> 4, c4 = i & 15;
        *(float4*)(Ps + r * RW + c4 * 4) =
            *(const float4*)(Qg + (size_t)(q0 + r) * DH + c4 * 4);
    }
    __syncthreads();

    uint32_t qf[2][8][4];
    {
        const uint32_t aQ0 = ps_u + (uint32_t)((w * 32 + (l & 15)) * RW + (l >> 4) * 4) * 4u;
#pragma unroll
        for (int mt = 0; mt < 2; mt++)
#pragma unroll
            for (int kk = 0; kk < 8; kk++)
                ldsm_x4(qf[mt][kk][0], qf[mt][kk][1], qf[mt][kk][2], qf[mt][kk][3],
                        aQ0 + (uint32_t)(mt * 16 * RW) * 4u + kk * 32u);
    }

    float o[2][8][4];
#pragma unroll
    for (int mt = 0; mt < 2; mt++)
#pragma unroll
        for (int n = 0; n < 8; n++)
#pragma unroll
            for (int j = 0; j < 4; j++) o[mt][n][j] = 0.f;
    float mr[4], lr[4];
#pragma unroll
    for (int i = 0; i < 4; i++) { mr[i] = -1e30f; lr[i] = 0.f; }

    const int NT = SS / 64;
    for (int t = 0; t < NT; t++) {
        const int buf = t & 1;
        const uint32_t kBase = sm_u + (uint32_t)K_OFF(buf) * 4u + bLane;
        const uint32_t vBase = sm_u + (uint32_t)V_OFF(buf) * 4u + bLane;

        if (t + 1 < NT) {
            const int nb = 1 - buf;
            const int nk0 = (t + 1) * 64;
#pragma unroll
            for (int it = 0; it < 8; it++) {
                const int idx = it * 128 + tid;
                const int r = idx >> 4, c = idx & 15;
                cpa16(sm_u + (uint32_t)(K_OFF(nb) + r * RW + c * 4) * 4u,
                      Kg + (size_t)(nk0 + r) * DH + c * 4);
            }
#pragma unroll
            for (int it = 0; it < 8; it++) {
                const int idx = it * 128 + tid;
                const int d = idx >> 4, c = idx & 15;
                cpa16(sm_u + (uint32_t)(V_OFF(nb) + d * RW + c * 4) * 4u,
                      VgT + (size_t)d * SS + nk0 + c * 4);
            }
            cpa_commit();
            cpa_wait<1>();
        } else {
            cpa_wait<0>();
        }
        __syncthreads();

        float s[2][8][4];
#pragma unroll
        for (int mt = 0; mt < 2; mt++)
#pragma unroll
            for (int n = 0; n < 8; n++)
#pragma unroll
                for (int j = 0; j < 4; j++) s[mt][n][j] = 0.f;

#pragma unroll
        for (int kk = 0; kk < 8; kk++) {
#pragma unroll
            for (int n = 0; n < 8; n++) {
                uint32_t b0, b1;
                ldsm_x2(b0, b1, kBase + (uint32_t)(n * 8 * RW) * 4u + kk * 32u);
                mma_tf32(s[0][n], qf[0][kk][0], qf[0][kk][1], qf[0][kk][2], qf[0][kk][3], b0, b1);
                mma_tf32(s[1][n], qf[1][kk][0], qf[1][kk][1], qf[1][kk][2], qf[1][kk][3], b0, b1);
            }
        }

        const int k0 = t * 64;
        float rx[4] = {-1e30f, -1e30f, -1e30f, -1e30f};
#pragma unroll
        for (int mt = 0; mt < 2; mt++)
#pragma unroll
            for (int n = 0; n < 8; n++) {
                const float mk0 = Ms[k0 + n * 8 + 2 * tg];
                const float mk1 = Ms[k0 + n * 8 + 2 * tg + 1];
                s[mt][n][0] += mk0; s[mt][n][1] += mk1;
                s[mt][n][2] += mk0; s[mt][n][3] += mk1;
                rx[mt * 2 + 0] = fmaxf(rx[mt * 2 + 0], fmaxf(s[mt][n][0], s[mt][n][1]));
                rx[mt * 2 + 1] = fmaxf(rx[mt * 2 + 1], fmaxf(s[mt][n][2], s[mt][n][3]));
            }
#pragma unroll
        for (int i = 0; i < 4; i++) {
            rx[i] = fmaxf(rx[i], __shfl_xor_sync(0xffffffffu, rx[i], 1));
            rx[i] = fmaxf(rx[i], __shfl_xor_sync(0xffffffffu, rx[i], 2));
        }
        float mn[4], cc[4], sum[4];
#pragma unroll
        for (int i = 0; i < 4; i++) {
            mn[i] = fmaxf(mr[i], rx[i]);
            cc[i] = __expf(mr[i] - mn[i]);
            sum[i] = 0.f;
        }
        const int rowb = w * 32 + grp;
#pragma unroll
        for (int mt = 0; mt < 2; mt++) {
            const int r0 = rowb + mt * 16;
#pragma unroll
            for (int n = 0; n < 8; n++) {
                const float p00 = __expf(s[mt][n][0] - mn[mt * 2]);
                const float p01 = __expf(s[mt][n][1] - mn[mt * 2]);
                const float p10 = __expf(s[mt][n][2] - mn[mt * 2 + 1]);
                const float p11 = __expf(s[mt][n][3] - mn[mt * 2 + 1]);
                sum[mt * 2]     += p00 + p01;
                sum[mt * 2 + 1] += p10 + p11;
                *(float2*)(Ps + r0 * RW + n * 8 + 2 * tg)       = make_float2(tf32r(p00), tf32r(p01));
                *(float2*)(Ps + (r0 + 8) * RW + n * 8 + 2 * tg) = make_float2(tf32r(p10), tf32r(p11));
            }
        }
#pragma unroll
        for (int i = 0; i < 4; i++) {
            sum[i] += __shfl_xor_sync(0xffffffffu, sum[i], 1);
            sum[i] += __shfl_xor_sync(0xffffffffu, sum[i], 2);
            lr[i] = lr[i] * cc[i] + sum[i];
            mr[i] = mn[i];
        }
#pragma unroll
        for (int mt = 0; mt < 2; mt++)
#pragma unroll
            for (int n = 0; n < 8; n++) {
                o[mt][n][0] *= cc[mt * 2];     o[mt][n][1] *= cc[mt * 2];
                o[mt][n][2] *= cc[mt * 2 + 1]; o[mt][n][3] *= cc[mt * 2 + 1];
            }
        __syncwarp();

#pragma unroll
        for (int kk = 0; kk < 8; kk++) {
            uint32_t a0[4], a1[4];
            ldsm_x4(a0[0], a0[1], a0[2], a0[3], aP0 + kk * 32u);
            ldsm_x4(a1[0], a1[1], a1[2], a1[3], aP1 + kk * 32u);
#pragma unroll
            for (int n = 0; n < 8; n++) {
                uint32_t b0, b1;
                ldsm_x2(b0, b1, vBase + (uint32_t)(n * 8 * RW) * 4u + kk * 32u);
                mma_tf32(o[0][n], a0[0], a0[1], a0[2], a0[3], b0, b1);
                mma_tf32(o[1][n], a1[0], a1[1], a1[2], a1[3], b0, b1);
            }
        }
        __syncthreads();
    }

#pragma unroll
    for (int mt = 0; mt < 2; mt++) {
#pragma unroll
        for (int half = 0; half < 2; half++) {
            const int i = mt * 2 + half;
            const float inv = 1.0f / lr[i];
            const int r = q0 + w * 32 + mt * 16 + half * 8 + grp;
#pragma unroll
            for (int n = 0; n < 8; n++) {
                const int col = h * DH + n * 8 + 2 * tg;
                *(float2*)(out + (size_t)(b * SS + r) * DD + col) =
                    make_float2(o[mt][n][half * 2] * inv, o[mt][n][half * 2 + 1] * inv);
            }
        }
    }
}

// ---------------------------------------------------------------------------
extern "C" void kernel_launch(void* const* d_in, const int* in_sizes, int n_in,
                              void* d_out, int out_size)
{
    const float* hidden = (const float*)d_in[0];
    const float* mask   = (const float*)d_in[1];
    const float* Wq     = (const float*)d_in[2];
    const float* bq     = (const float*)d_in[3];
    const float* Wk     = (const float*)d_in[4];
    const float* bk     = (const float*)d_in[5];
    const float* Wv     = (const float*)d_in[6];
    const float* bv     = (const float*)d_in[7];
    float* out = (float*)d_out;

    const int smem_qkv  = QKV_SMF * sizeof(float);   // 73728 B
    const int smem_attn = SMF * sizeof(float);       // 112640 B
    cudaFuncSetAttribute(qkv_kernel,  cudaFuncAttributeMaxDynamicSharedMemorySize, smem_qkv);
    cudaFuncSetAttribute(attn_kernel, cudaFuncAttributeMaxDynamicSharedMemorySize, smem_attn);

    prep_w<<<dim3(DD / 32, DD / 32, 3), dim3(32, 8)>>>(Wq, Wk, Wv);
    prep_x<<<(BB * SS * DD / 4) / 256, 256>>>(hidden);
    qkv_kernel<<<dim3(64, 6, 3), 256, smem_qkv>>>(bq, bk, bv);
    attn_kernel<<<dim3(SS / 128, BH), 128, smem_attn>>>(mask, out);
}